// round 1
// baseline (speedup 1.0000x reference)
#include <cuda_runtime.h>

#define NMAPS   128      // 4*32
#define H       480
#define W       640
#define GRID_N  10
#define CH      48       // H/GRID
#define CW      64       // W/GRID
#define CELLS   100      // GRID*GRID
#define CELL_ELEMS (CH*CW)   // 3072

// Scratch (no device allocation allowed in kernel_launch)
__device__ float g_cand_score[NMAPS * CELLS];
__device__ int   g_cand_gr[NMAPS * CELLS];
__device__ int   g_cand_gc[NMAPS * CELLS];

// argmax combine: larger value wins; exact tie -> smaller flat index (first occurrence)
__device__ __forceinline__ void combine(float& bv, int& bi, float v, int i) {
    if (v > bv || (v == bv && i < bi)) { bv = v; bi = i; }
}

__global__ __launch_bounds__(256) void cell_argmax_kernel(const float* __restrict__ s) {
    const int cell = blockIdx.x;          // 0 .. NMAPS*CELLS-1
    const int map  = cell / CELLS;
    const int cidx = cell - map * CELLS;
    const int ci   = cidx / GRID_N;       // row block
    const int cj   = cidx - ci * GRID_N;  // col block

    const float* mbase = s + (size_t)map * (H * W);
    // Cell base: row stride W floats; cj*CW = 256B aligned -> float4 safe
    const float4* base = reinterpret_cast<const float4*>(mbase + (size_t)ci * CH * W + cj * CW);

    const int tid = threadIdx.x;
    float bv = -3.402823466e38f;
    int   bi = 0x7fffffff;

    // 768 float4 per cell; 256 threads -> 3 vec loads each, coalesced
    #pragma unroll
    for (int it = 0; it < 3; ++it) {
        int q  = tid + it * 256;          // float4 index within cell
        int lr = q >> 4;                  // 16 float4 per 64-float row
        int lq = q & 15;
        float4 v = base[lr * (W / 4) + lq];
        int f = q << 2;                   // flat element index (row-major within cell)
        combine(bv, bi, v.x, f);
        combine(bv, bi, v.y, f + 1);
        combine(bv, bi, v.z, f + 2);
        combine(bv, bi, v.w, f + 3);
    }

    // warp reduce
    #pragma unroll
    for (int off = 16; off > 0; off >>= 1) {
        float ov = __shfl_down_sync(0xffffffffu, bv, off);
        int   oi = __shfl_down_sync(0xffffffffu, bi, off);
        combine(bv, bi, ov, oi);
    }
    __shared__ float sv[8];
    __shared__ int   si[8];
    const int w = tid >> 5;
    if ((tid & 31) == 0) { sv[w] = bv; si[w] = bi; }
    __syncthreads();
    if (tid == 0) {
        bv = sv[0]; bi = si[0];
        #pragma unroll
        for (int k = 1; k < 8; ++k) combine(bv, bi, sv[k], si[k]);
        int lr = bi >> 6;                 // bi / CW
        int lc = bi & 63;                 // bi % CW
        int gr = ci * CH + lr; gr = gr < 1 ? 1 : (gr > H - 2 ? H - 2 : gr);
        int gc = cj * CW + lc; gc = gc < 1 ? 1 : (gc > W - 2 ? W - 2 : gc);
        // score is read at the CLAMPED coordinate (faithful to reference)
        g_cand_score[cell] = mbase[gr * W + gc];
        g_cand_gr[cell]    = gr;
        g_cand_gc[cell]    = gc;
    }
}

// Top-n of 100 candidates per map, jax.lax.top_k semantics:
// descending by value, ties broken by ascending candidate index.
__global__ __launch_bounds__(128) void topk_kernel(float* __restrict__ out, int top_n) {
    const int map = blockIdx.x;
    const int t   = threadIdx.x;

    __shared__ unsigned long long keys[CELLS];

    float myscore = 0.f;
    int   mygr = 0, mygc = 0;
    unsigned long long mykey = 0;

    if (t < CELLS) {
        myscore = g_cand_score[map * CELLS + t];
        mygr    = g_cand_gr[map * CELLS + t];
        mygc    = g_cand_gc[map * CELLS + t];
        unsigned u = __float_as_uint(myscore);
        unsigned mono = (u & 0x80000000u) ? ~u : (u | 0x80000000u);  // order-preserving
        mykey = ((unsigned long long)mono << 32) | (unsigned)(CELLS - 1 - t);
        keys[t] = mykey;
    }
    __syncthreads();

    if (t < CELLS) {
        int rank = 0;
        #pragma unroll 10
        for (int j = 0; j < CELLS; ++j) rank += (keys[j] > mykey);
        if (rank < top_n) {
            const int o = map * top_n + rank;
            out[o]                       = (float)mygr;   // x = row indices
            out[NMAPS * top_n + o]       = (float)mygc;   // y = col indices
            out[2 * NMAPS * top_n + o]   = myscore;       // scores
        }
    }
}

extern "C" void kernel_launch(void* const* d_in, const int* in_sizes, int n_in,
                              void* d_out, int out_size) {
    const float* s = (const float*)d_in[0];
    // out = concat(x[128*top_n], y[128*top_n], scores[128*top_n]) as float32
    int top_n = out_size / (3 * NMAPS);
    cell_argmax_kernel<<<NMAPS * CELLS, 256>>>(s);
    topk_kernel<<<NMAPS, 128>>>((float*)d_out, top_n);
}